// round 14
// baseline (speedup 1.0000x reference)
#include <cuda_runtime.h>

// CRF forward loss + argmax decode, B=64, C=2, T=65536 (H=W=256).
//
// Single kernel, 1024 blocks (16/batch), 6 blocks/SM (forced 42 regs).
// Per block: stage 32KB logits into XOR-swizzled smem; each thread folds a
// 16-step chunk as TWO interleaved 8-step linear 2x2 chains (ILP) with
// emission-difference factoring (exp(e0) folded into a scalar log
// accumulator; 16 MUFU/thread). Emissions are consumed in TWO phases
// (half the floats live at a time -> fits 42 regs). Exact pow2 rescale at
// chain ends; warp+block reduction in LINEAR space (matmul + pow2 rescale,
// log-scale carried as float). Last-block ticket folds 16 mats/batch in log
// space, applies alpha0, tree-sums 64 lls. Decode fused via smem, coalesced
// scalar stores (d_out+1 is only 4B-aligned).

#define NB 64
#define NT 65536
#define NK 4096
#define NL 16
#define NBLK (NB * NK / 256)   // 1024 blocks, 16 per batch
#define LN2F 0.6931471805599453f

typedef unsigned long long ull;

__device__ float4 g_mats[NBLK];  // per-block 2x2 log-matrices (x=00 y=01 z=10 w=11)
__device__ int    g_sem;         // last-block ticket (winner resets)

// ---- packed f32x2 helpers ----
__device__ __forceinline__ ull packxy(float lo, float hi) {
    ull r; asm("mov.b64 %0, {%1, %2};" : "=l"(r) : "f"(lo), "f"(hi)); return r;
}
__device__ __forceinline__ ull pack2(float x) { return packxy(x, x); }
__device__ __forceinline__ void unpack2(ull a, float& lo, float& hi) {
    asm("mov.b64 {%0, %1}, %2;" : "=f"(lo), "=f"(hi) : "l"(a));
}
__device__ __forceinline__ ull mul2(ull a, ull b) {
    ull r; asm("mul.rn.f32x2 %0, %1, %2;" : "=l"(r) : "l"(a), "l"(b)); return r;
}
__device__ __forceinline__ ull fma2(ull a, ull b, ull c) {
    ull r; asm("fma.rn.f32x2 %0, %1, %2, %3;" : "=l"(r) : "l"(a), "l"(b), "l"(c)); return r;
}

struct TransP { ull T00, T10, T01, T11; };  // T'[src][dst] = exp(trans[dst*2+src])

// One linear step, exp(e0) factored out (tracked in a scalar log-sum):
//   col0' = col0*T00 + col1*T10
//   col1' = (col0*T01 + col1*T11) * exp(e1-e0)
__device__ __forceinline__ void stepd(float d, ull& col0, ull& col1, const TransP& cs) {
    ull E = pack2(__expf(d));
    ull n0 = fma2(col0, cs.T00, mul2(col1, cs.T10));
    ull n1 = mul2(fma2(col0, cs.T01, mul2(col1, cs.T11)), E);
    col0 = n0; col1 = n1;
}

// Exact power-of-2 rescale; accumulate ex*ln2 into ls. Max entry -> [1,2).
__device__ __forceinline__ void rescale(ull& c0, ull& c1, float& ls) {
    float a, b, c, d;
    unpack2(c0, a, b);
    unpack2(c1, c, d);
    float mx = fmaxf(fmaxf(a, b), fmaxf(c, d));
    int ex = ((__float_as_int(mx) >> 23) & 0xFF) - 127;
    ull scp = pack2(__int_as_float((127 - ex) << 23));
    c0 = mul2(c0, scp);
    c1 = mul2(c1, scp);
    ls += (float)ex * LN2F;
}

// Linear 2x2 combine, self(earlier) . other(later), then rescale.
__device__ __forceinline__ void combLin(ull& c0, ull& c1, float& ls,
                                        ull o0, ull o1, float ols) {
    float q00, q10, q01, q11;
    unpack2(o0, q00, q10);
    unpack2(o1, q01, q11);
    ull r0 = fma2(c0, pack2(q00), mul2(c1, pack2(q10)));
    ull r1 = fma2(c0, pack2(q01), mul2(c1, pack2(q11)));
    c0 = r0; c1 = r1;
    ls += ols;
    rescale(c0, c1, ls);
}

// ---- log-semiring (winner block only) ----
__device__ __forceinline__ float lse2(float x, float y) {
    float m = fmaxf(x, y);
    float d = fminf(x, y) - m;
    return m + __logf(1.f + __expf(d));
}
__device__ __forceinline__ float4 combM(float4 A, float4 Bv) {
    float4 C;
    C.x = lse2(A.x + Bv.x, A.y + Bv.z);
    C.y = lse2(A.x + Bv.y, A.y + Bv.w);
    C.z = lse2(A.z + Bv.x, A.w + Bv.z);
    C.w = lse2(A.z + Bv.y, A.w + Bv.w);
    return C;
}
__device__ __forceinline__ float4 shfl4(float4 v, int off, int w) {
    float4 r;
    r.x = __shfl_down_sync(0xffffffffu, v.x, off, w);
    r.y = __shfl_down_sync(0xffffffffu, v.y, off, w);
    r.z = __shfl_down_sync(0xffffffffu, v.z, off, w);
    r.w = __shfl_down_sync(0xffffffffu, v.w, off, w);
    return r;
}

// XOR swizzle over float4 index: conflict-free for coalesced column-writes
// and per-thread row-reads.
__device__ __forceinline__ int swz(int L) {
    return (L & ~3) | ((L ^ (L >> 2) ^ (L >> 4)) & 3);
}

__device__ __forceinline__ float4 dec4(float4 A, float4 B) {
    float4 d;
    d.x = (B.x > A.x) ? 1.f : 0.f;
    d.y = (B.y > A.y) ? 1.f : 0.f;
    d.z = (B.z > A.z) ? 1.f : 0.f;
    d.w = (B.w > A.w) ? 1.f : 0.f;
    return d;
}

// ============================================================================
__global__ void __launch_bounds__(256, 6) crf_fused(const float* __restrict__ logits,
                                                    const float* __restrict__ trans,
                                                    float* __restrict__ dec,
                                                    float* __restrict__ loss_out) {
    __shared__ float4 S0[1024];   // 16KB: state-0 emissions (swizzled)
    __shared__ float4 S1[1024];   // 16KB: state-1 emissions, then decode
    __shared__ ull    WMc0[8], WMc1[8];
    __shared__ float  WMls[8];
    __shared__ float  sll[NB];
    __shared__ int    sWin;

    int tid = threadIdx.x;
    int b   = blockIdx.x >> 4;
    int cb  = (blockIdx.x & 15) * 256;
    const float* r0 = logits + ((size_t)(2 * b)    ) * NT + (size_t)cb * NL;
    const float* r1 = logits + ((size_t)(2 * b) + 1) * NT + (size_t)cb * NL;
    float*       pd = dec + (size_t)b * NT + (size_t)cb * NL;  // 4B-aligned only

    const float4* g0 = reinterpret_cast<const float4*>(r0);
    const float4* g1 = reinterpret_cast<const float4*>(r1);
#pragma unroll
    for (int i = 0; i < 4; ++i) {
        int L = i * 256 + tid;
        S0[swz(L)] = g0[L];
        S1[swz(L)] = g1[L];
    }

    TransP cs;
    cs.T00 = pack2(__expf(trans[0]));
    cs.T10 = pack2(__expf(trans[1]));
    cs.T01 = pack2(__expf(trans[2]));
    cs.T11 = pack2(__expf(trans[3]));

    __syncthreads();

    int s = (tid ^ (tid >> 2)) & 3;
    const bool skip0 = (blockIdx.x == 0 && tid == 0);  // global t=0: alpha0 at end

    ull P0 = packxy(1.f, 0.f), P1 = packxy(0.f, 1.f);
    ull Q0 = packxy(1.f, 0.f), Q1 = packxy(0.f, 1.f);
    float lsP, lsQ;

    // ---- Phase A: emissions 0^s, 2^s (P steps 1-4, Q steps 1-4) ----
    {
        float4 A0 = S0[4 * tid + (0 ^ s)], B0 = S1[4 * tid + (0 ^ s)];
        float4 A2 = S0[4 * tid + (2 ^ s)], B2 = S1[4 * tid + (2 ^ s)];
        S1[4 * tid + (0 ^ s)] = dec4(A0, B0);    // own region, regs hold B
        S1[4 * tid + (2 ^ s)] = dec4(A2, B2);

        float e00 = skip0 ? 0.f : A0.x;
        lsP = (e00  + A0.y) + (A0.z + A0.w);
        lsQ = (A2.x + A2.y) + (A2.z + A2.w);

        if (!skip0) stepd(B0.x - A0.x, P0, P1, cs);
        stepd(B2.x - A2.x, Q0, Q1, cs);
        stepd(B0.y - A0.y, P0, P1, cs);
        stepd(B2.y - A2.y, Q0, Q1, cs);
        stepd(B0.z - A0.z, P0, P1, cs);
        stepd(B2.z - A2.z, Q0, Q1, cs);
        stepd(B0.w - A0.w, P0, P1, cs);
        stepd(B2.w - A2.w, Q0, Q1, cs);
    }

    // ---- Phase B: emissions 1^s, 3^s (P steps 5-8, Q steps 5-8) ----
    {
        float4 A1 = S0[4 * tid + (1 ^ s)], B1 = S1[4 * tid + (1 ^ s)];
        float4 A3 = S0[4 * tid + (3 ^ s)], B3 = S1[4 * tid + (3 ^ s)];
        S1[4 * tid + (1 ^ s)] = dec4(A1, B1);
        S1[4 * tid + (3 ^ s)] = dec4(A3, B3);

        lsP += (A1.x + A1.y) + (A1.z + A1.w);
        lsQ += (A3.x + A3.y) + (A3.z + A3.w);

        stepd(B1.x - A1.x, P0, P1, cs);
        stepd(B3.x - A3.x, Q0, Q1, cs);
        stepd(B1.y - A1.y, P0, P1, cs);
        stepd(B3.y - A3.y, Q0, Q1, cs);
        stepd(B1.z - A1.z, P0, P1, cs);
        stepd(B3.z - A3.z, Q0, Q1, cs);
        stepd(B1.w - A1.w, P0, P1, cs);
        stepd(B3.w - A3.w, Q0, Q1, cs);
    }

    // Normalize each chain, then combine P(earlier).Q(later) + rescale.
    rescale(P0, P1, lsP);
    rescale(Q0, Q1, lsQ);
    combLin(P0, P1, lsP, Q0, Q1, lsQ);   // result in P*, lsP

    // Ordered warp tree in LINEAR space (lane 0 ends with 32-chunk product).
#pragma unroll
    for (int off = 1; off < 32; off <<= 1) {
        ull  o0  = __shfl_down_sync(0xffffffffu, P0, off, 32);
        ull  o1  = __shfl_down_sync(0xffffffffu, P1, off, 32);
        float ol = __shfl_down_sync(0xffffffffu, lsP, off, 32);
        combLin(P0, P1, lsP, o0, o1, ol);
    }
    if ((tid & 31) == 0) {
        WMc0[tid >> 5] = P0;
        WMc1[tid >> 5] = P1;
        WMls[tid >> 5] = lsP;
    }
    __syncthreads();   // also orders decode S1 writes vs flush

    // Block tree: warp 0 folds 8 warp-mats (width-8 ordered shfl tree).
    if (tid < 32) {
        ull  c0 = WMc0[tid & 7];
        ull  c1 = WMc1[tid & 7];
        float ls = WMls[tid & 7];
#pragma unroll
        for (int off = 1; off < 8; off <<= 1) {
            ull  o0  = __shfl_down_sync(0xffffffffu, c0, off, 8);
            ull  o1  = __shfl_down_sync(0xffffffffu, c1, off, 8);
            float ol = __shfl_down_sync(0xffffffffu, ls, off, 8);
            combLin(c0, c1, ls, o0, o1, ol);
        }
        if (tid == 0) {
            float m00, m10, m01, m11;
            unpack2(c0, m00, m10);
            unpack2(c1, m01, m11);
            float4 m;
            m.x = __logf(m00) + ls;
            m.y = __logf(m01) + ls;
            m.z = __logf(m10) + ls;
            m.w = __logf(m11) + ls;
            g_mats[blockIdx.x] = m;
            __threadfence();
        }
    }

    // Flush decode: conflict-free scalar LDS + fully coalesced STG.32
    const float* S1f = reinterpret_cast<const float*>(S1);
#pragma unroll
    for (int i = 0; i < 16; ++i) {
        int F = i * 256 + tid;
        pd[F] = S1f[swz(F >> 2) * 4 + (F & 3)];
    }

    if (tid == 0) {
        int t = atomicAdd(&g_sem, 1);
        sWin = (t == NBLK - 1);
    }
    __syncthreads();
    if (!sWin) return;

    // ======== winner block: final combine (log space, time-ordered) ========
    {
        int bb2 = tid >> 2;           // batch (4 threads per batch)
        int q   = tid & 3;
        const float4* base = g_mats + bb2 * 16 + q * 4;
        float4 v0 = base[0], v1 = base[1], v2 = base[2], v3 = base[3];
        float4 mm = combM(combM(v0, v1), combM(v2, v3));
        mm = combM(mm, shfl4(mm, 1, 4));
        mm = combM(mm, shfl4(mm, 2, 4));
        if (q == 0) {
            float a0 = logits[(size_t)(2 * bb2)     * NT];  // alpha0[0]
            float a1 = logits[(size_t)(2 * bb2 + 1) * NT];  // alpha0[1]
            float w0 = lse2(a0 + mm.x, a1 + mm.z);
            float w1 = lse2(a0 + mm.y, a1 + mm.w);
            sll[bb2] = lse2(w0, w1);
        }
    }
    __syncthreads();
    if (tid < 32) {
        float v = sll[tid] + sll[tid + 32];
#pragma unroll
        for (int off = 16; off >= 1; off >>= 1)
            v += __shfl_down_sync(0xffffffffu, v, off, 32);
        if (tid == 0) {
            if (loss_out != nullptr) loss_out[0] = -v / (float)NB;
            g_sem = 0;   // reset for next graph replay
        }
    }
}

extern "C" void kernel_launch(void* const* d_in, const int* in_sizes, int n_in,
                              void* d_out, int out_size) {
    const float* logits = (const float*)d_in[0];
    // d_in[1] = mask (all-ones; unused by the reference math)
    const float* trans  = (const float*)d_in[2];
    float* out = (float*)d_out;

    int base = out_size - NB * NT;   // expected 1 (loss scalar before decoded)
    if (base < 0) base = 0;

    crf_fused<<<NBLK, 256>>>(logits, trans, out + base, base > 0 ? out : nullptr);
}

// round 16
// speedup vs baseline: 1.0194x; 1.0194x over previous
#include <cuda_runtime.h>

// CRF forward loss + argmax decode, B=64, C=2, T=65536 (H=W=256).
//
// Single kernel, 1024 blocks (16/batch). Per block: cp.async-stage 32KB of
// logits into XOR-swizzled smem; each thread folds a 16-step chunk as TWO
// interleaved 8-step linear 2x2 chains (emission-difference factoring:
// exp(e0) folded into a scalar log accumulator, 16 MUFU/thread). Exact pow2
// rescale at chain ends. Warp tree (5 levels) and block tree (3 levels) run
// in LINEAR space WITHOUT per-level rescale (growth bound 2^63 / 2^15 from
// normalized inputs -> no overflow; ratios bounded -> no underflow), with
// one rescale between the trees. Last-block ticket folds 16 mats/batch in
// log space, applies alpha0, tree-sums 64 lls. Decode fused via smem,
// coalesced scalar stores (d_out+1 is only 4B-aligned).

#define NB 64
#define NT 65536
#define NK 4096
#define NL 16
#define NBLK (NB * NK / 256)   // 1024 blocks, 16 per batch
#define LN2F 0.6931471805599453f

typedef unsigned long long ull;

__device__ float4 g_mats[NBLK];  // per-block 2x2 log-matrices (x=00 y=01 z=10 w=11)
__device__ int    g_sem;         // last-block ticket (winner resets)

// ---- packed f32x2 helpers ----
__device__ __forceinline__ ull packxy(float lo, float hi) {
    ull r; asm("mov.b64 %0, {%1, %2};" : "=l"(r) : "f"(lo), "f"(hi)); return r;
}
__device__ __forceinline__ ull pack2(float x) { return packxy(x, x); }
__device__ __forceinline__ void unpack2(ull a, float& lo, float& hi) {
    asm("mov.b64 {%0, %1}, %2;" : "=f"(lo), "=f"(hi) : "l"(a));
}
__device__ __forceinline__ ull mul2(ull a, ull b) {
    ull r; asm("mul.rn.f32x2 %0, %1, %2;" : "=l"(r) : "l"(a), "l"(b)); return r;
}
__device__ __forceinline__ ull fma2(ull a, ull b, ull c) {
    ull r; asm("fma.rn.f32x2 %0, %1, %2, %3;" : "=l"(r) : "l"(a), "l"(b), "l"(c)); return r;
}
__device__ __forceinline__ unsigned smem_u32(const void* p) {
    unsigned a;
    asm("{ .reg .u64 t; cvta.to.shared.u64 t, %1; cvt.u32.u64 %0, t; }" : "=r"(a) : "l"(p));
    return a;
}

struct TransP { ull T00, T10, T01, T11; };  // T'[src][dst] = exp(trans[dst*2+src])

// One linear step, exp(e0) factored out (tracked in a scalar log-sum):
//   col0' = col0*T00 + col1*T10
//   col1' = (col0*T01 + col1*T11) * exp(e1-e0)
__device__ __forceinline__ void stepd(float d, ull& col0, ull& col1, const TransP& cs) {
    ull E = pack2(__expf(d));
    ull n0 = fma2(col0, cs.T00, mul2(col1, cs.T10));
    ull n1 = mul2(fma2(col0, cs.T01, mul2(col1, cs.T11)), E);
    col0 = n0; col1 = n1;
}

// Exact power-of-2 rescale; accumulate ex*ln2 into ls. Max entry -> [1,2).
__device__ __forceinline__ void rescale(ull& c0, ull& c1, float& ls) {
    float a, b, c, d;
    unpack2(c0, a, b);
    unpack2(c1, c, d);
    float mx = fmaxf(fmaxf(a, b), fmaxf(c, d));
    int ex = ((__float_as_int(mx) >> 23) & 0xFF) - 127;
    ull scp = pack2(__int_as_float((127 - ex) << 23));
    c0 = mul2(c0, scp);
    c1 = mul2(c1, scp);
    ls += (float)ex * LN2F;
}

// Linear 2x2 combine, self(earlier) . other(later). NO rescale (tree-safe).
__device__ __forceinline__ void combLinN(ull& c0, ull& c1, float& ls,
                                         ull o0, ull o1, float ols) {
    float q00, q10, q01, q11;
    unpack2(o0, q00, q10);
    unpack2(o1, q01, q11);
    ull r0 = fma2(c0, pack2(q00), mul2(c1, pack2(q10)));
    ull r1 = fma2(c0, pack2(q01), mul2(c1, pack2(q11)));
    c0 = r0; c1 = r1;
    ls += ols;
}

// ---- log-semiring (winner block only) ----
__device__ __forceinline__ float lse2(float x, float y) {
    float m = fmaxf(x, y);
    float d = fminf(x, y) - m;
    return m + __logf(1.f + __expf(d));
}
__device__ __forceinline__ float4 combM(float4 A, float4 Bv) {
    float4 C;
    C.x = lse2(A.x + Bv.x, A.y + Bv.z);
    C.y = lse2(A.x + Bv.y, A.y + Bv.w);
    C.z = lse2(A.z + Bv.x, A.w + Bv.z);
    C.w = lse2(A.z + Bv.y, A.w + Bv.w);
    return C;
}
__device__ __forceinline__ float4 shfl4(float4 v, int off, int w) {
    float4 r;
    r.x = __shfl_down_sync(0xffffffffu, v.x, off, w);
    r.y = __shfl_down_sync(0xffffffffu, v.y, off, w);
    r.z = __shfl_down_sync(0xffffffffu, v.z, off, w);
    r.w = __shfl_down_sync(0xffffffffu, v.w, off, w);
    return r;
}

// XOR swizzle over float4 index: conflict-free for coalesced column-writes
// and per-thread row-reads.
__device__ __forceinline__ int swz(int L) {
    return (L & ~3) | ((L ^ (L >> 2) ^ (L >> 4)) & 3);
}

// ============================================================================
__global__ void __launch_bounds__(256) crf_fused(const float* __restrict__ logits,
                                                 const float* __restrict__ trans,
                                                 float* __restrict__ dec,
                                                 float* __restrict__ loss_out) {
    __shared__ float4 S0[1024];   // 16KB: state-0 emissions (swizzled)
    __shared__ float4 S1[1024];   // 16KB: state-1 emissions, then decode
    __shared__ ull    WMc0[8], WMc1[8];
    __shared__ float  WMls[8];
    __shared__ float  sll[NB];
    __shared__ int    sWin;

    int tid = threadIdx.x;
    int b   = blockIdx.x >> 4;
    int cb  = (blockIdx.x & 15) * 256;
    const float* r0 = logits + ((size_t)(2 * b)    ) * NT + (size_t)cb * NL;
    const float* r1 = logits + ((size_t)(2 * b) + 1) * NT + (size_t)cb * NL;
    float*       pd = dec + (size_t)b * NT + (size_t)cb * NL;  // 4B-aligned only

    // Stage via cp.async (LDGSTS): no register round-trip, no LDG scoreboard.
    {
        const float4* g0 = reinterpret_cast<const float4*>(r0);
        const float4* g1 = reinterpret_cast<const float4*>(r1);
#pragma unroll
        for (int i = 0; i < 4; ++i) {
            int L = i * 256 + tid;
            unsigned d0 = smem_u32(&S0[swz(L)]);
            unsigned d1 = smem_u32(&S1[swz(L)]);
            asm volatile("cp.async.cg.shared.global [%0], [%1], 16;" :: "r"(d0), "l"(g0 + L));
            asm volatile("cp.async.cg.shared.global [%0], [%1], 16;" :: "r"(d1), "l"(g1 + L));
        }
        asm volatile("cp.async.commit_group;");
    }

    TransP cs;
    cs.T00 = pack2(__expf(trans[0]));
    cs.T10 = pack2(__expf(trans[1]));
    cs.T01 = pack2(__expf(trans[2]));
    cs.T11 = pack2(__expf(trans[3]));

    asm volatile("cp.async.wait_group 0;" ::: "memory");
    __syncthreads();

    int s = (tid ^ (tid >> 2)) & 3;
    float4 A0 = S0[4 * tid + (0 ^ s)], A1 = S0[4 * tid + (1 ^ s)];
    float4 A2 = S0[4 * tid + (2 ^ s)], A3 = S0[4 * tid + (3 ^ s)];
    float4 B0 = S1[4 * tid + (0 ^ s)], B1 = S1[4 * tid + (1 ^ s)];
    float4 B2 = S1[4 * tid + (2 ^ s)], B3 = S1[4 * tid + (3 ^ s)];

    // Decode into own S1 region (registers already hold B*, no hazard).
    {
        float4 d;
        d.x = (B0.x > A0.x) ? 1.f : 0.f; d.y = (B0.y > A0.y) ? 1.f : 0.f;
        d.z = (B0.z > A0.z) ? 1.f : 0.f; d.w = (B0.w > A0.w) ? 1.f : 0.f;
        S1[4 * tid + (0 ^ s)] = d;
        d.x = (B1.x > A1.x) ? 1.f : 0.f; d.y = (B1.y > A1.y) ? 1.f : 0.f;
        d.z = (B1.z > A1.z) ? 1.f : 0.f; d.w = (B1.w > A1.w) ? 1.f : 0.f;
        S1[4 * tid + (1 ^ s)] = d;
        d.x = (B2.x > A2.x) ? 1.f : 0.f; d.y = (B2.y > A2.y) ? 1.f : 0.f;
        d.z = (B2.z > A2.z) ? 1.f : 0.f; d.w = (B2.w > A2.w) ? 1.f : 0.f;
        S1[4 * tid + (2 ^ s)] = d;
        d.x = (B3.x > A3.x) ? 1.f : 0.f; d.y = (B3.y > A3.y) ? 1.f : 0.f;
        d.z = (B3.z > A3.z) ? 1.f : 0.f; d.w = (B3.w > A3.w) ? 1.f : 0.f;
        S1[4 * tid + (3 ^ s)] = d;
    }

    const bool skip0 = (blockIdx.x == 0 && tid == 0);  // global t=0: alpha0 at end

    // Scalar log accumulators (off-chain FADDs) for the factored e0 sums.
    float e00 = skip0 ? 0.f : A0.x;
    float lsP = ((e00  + A0.y) + (A0.z + A0.w)) + ((A1.x + A1.y) + (A1.z + A1.w));
    float lsQ = ((A2.x + A2.y) + (A2.z + A2.w)) + ((A3.x + A3.y) + (A3.z + A3.w));

    // Chain P: steps 1..8, chain Q: steps 9..16 (independent -> 2x ILP).
    ull P0 = packxy(1.f, 0.f), P1 = packxy(0.f, 1.f);
    ull Q0 = packxy(1.f, 0.f), Q1 = packxy(0.f, 1.f);

    if (!skip0) stepd(B0.x - A0.x, P0, P1, cs);
    stepd(B2.x - A2.x, Q0, Q1, cs);
    stepd(B0.y - A0.y, P0, P1, cs);
    stepd(B2.y - A2.y, Q0, Q1, cs);
    stepd(B0.z - A0.z, P0, P1, cs);
    stepd(B2.z - A2.z, Q0, Q1, cs);
    stepd(B0.w - A0.w, P0, P1, cs);
    stepd(B2.w - A2.w, Q0, Q1, cs);
    stepd(B1.x - A1.x, P0, P1, cs);
    stepd(B3.x - A3.x, Q0, Q1, cs);
    stepd(B1.y - A1.y, P0, P1, cs);
    stepd(B3.y - A3.y, Q0, Q1, cs);
    stepd(B1.z - A1.z, P0, P1, cs);
    stepd(B3.z - A3.z, Q0, Q1, cs);
    stepd(B1.w - A1.w, P0, P1, cs);
    stepd(B3.w - A3.w, Q0, Q1, cs);

    // Normalize chains; combine P(earlier).Q(later); normalize result.
    rescale(P0, P1, lsP);
    rescale(Q0, Q1, lsQ);
    combLinN(P0, P1, lsP, Q0, Q1, lsQ);
    rescale(P0, P1, lsP);   // tree inputs normalized: max in [1,2)

    // Ordered warp tree, LINEAR, NO per-level rescale:
    // 5 levels from normalized inputs -> max <= 2^63 (no overflow).
#pragma unroll
    for (int off = 1; off < 32; off <<= 1) {
        ull  o0  = __shfl_down_sync(0xffffffffu, P0, off, 32);
        ull  o1  = __shfl_down_sync(0xffffffffu, P1, off, 32);
        float ol = __shfl_down_sync(0xffffffffu, lsP, off, 32);
        combLinN(P0, P1, lsP, o0, o1, ol);
    }
    if ((tid & 31) == 0) {
        rescale(P0, P1, lsP);        // normalize for the block tree
        WMc0[tid >> 5] = P0;
        WMc1[tid >> 5] = P1;
        WMls[tid >> 5] = lsP;
    }
    __syncthreads();   // also orders decode S1 writes vs flush

    // Block tree: warp 0 folds 8 warp-mats; 3 levels no-rescale (<= 2^15).
    if (tid < 32) {
        ull  c0 = WMc0[tid & 7];
        ull  c1 = WMc1[tid & 7];
        float ls = WMls[tid & 7];
#pragma unroll
        for (int off = 1; off < 8; off <<= 1) {
            ull  o0  = __shfl_down_sync(0xffffffffu, c0, off, 8);
            ull  o1  = __shfl_down_sync(0xffffffffu, c1, off, 8);
            float ol = __shfl_down_sync(0xffffffffu, ls, off, 8);
            combLinN(c0, c1, ls, o0, o1, ol);
        }
        if (tid == 0) {
            float m00, m10, m01, m11;
            unpack2(c0, m00, m10);
            unpack2(c1, m01, m11);
            float4 m;
            m.x = __logf(m00) + ls;
            m.y = __logf(m01) + ls;
            m.z = __logf(m10) + ls;
            m.w = __logf(m11) + ls;
            g_mats[blockIdx.x] = m;
            __threadfence();
        }
    }

    // Flush decode: conflict-free scalar LDS + fully coalesced STG.32
    const float* S1f = reinterpret_cast<const float*>(S1);
#pragma unroll
    for (int i = 0; i < 16; ++i) {
        int F = i * 256 + tid;
        pd[F] = S1f[swz(F >> 2) * 4 + (F & 3)];
    }

    if (tid == 0) {
        int t = atomicAdd(&g_sem, 1);
        sWin = (t == NBLK - 1);
    }
    __syncthreads();
    if (!sWin) return;

    // ======== winner block: final combine (log space, time-ordered) ========
    {
        int bb2 = tid >> 2;           // batch (4 threads per batch)
        int q   = tid & 3;
        const float4* base = g_mats + bb2 * 16 + q * 4;
        float4 v0 = base[0], v1 = base[1], v2 = base[2], v3 = base[3];
        float4 mm = combM(combM(v0, v1), combM(v2, v3));
        mm = combM(mm, shfl4(mm, 1, 4));
        mm = combM(mm, shfl4(mm, 2, 4));
        if (q == 0) {
            float a0 = logits[(size_t)(2 * bb2)     * NT];  // alpha0[0]
            float a1 = logits[(size_t)(2 * bb2 + 1) * NT];  // alpha0[1]
            float w0 = lse2(a0 + mm.x, a1 + mm.z);
            float w1 = lse2(a0 + mm.y, a1 + mm.w);
            sll[bb2] = lse2(w0, w1);
        }
    }
    __syncthreads();
    if (tid < 32) {
        float v = sll[tid] + sll[tid + 32];
#pragma unroll
        for (int off = 16; off >= 1; off >>= 1)
            v += __shfl_down_sync(0xffffffffu, v, off, 32);
        if (tid == 0) {
            if (loss_out != nullptr) loss_out[0] = -v / (float)NB;
            g_sem = 0;   // reset for next graph replay
        }
    }
}

extern "C" void kernel_launch(void* const* d_in, const int* in_sizes, int n_in,
                              void* d_out, int out_size) {
    const float* logits = (const float*)d_in[0];
    // d_in[1] = mask (all-ones; unused by the reference math)
    const float* trans  = (const float*)d_in[2];
    float* out = (float*)d_out;

    int base = out_size - NB * NT;   // expected 1 (loss scalar before decoded)
    if (base < 0) base = 0;

    crf_fused<<<NBLK, 256>>>(logits, trans, out + base, base > 0 ? out : nullptr);
}